// round 1
// baseline (speedup 1.0000x reference)
#include <cuda_runtime.h>
#include <math.h>

#define BATCH   8
#define L_SEQ   680
#define NHEADS  24
#define HDIM    64
#define CDIM    1536
#define MROWS   (BATCH * L_SEQ)      // 5440
#define QKVN    (3 * CDIM)           // 4608
#define SM_STRIDE 68

__device__ float g_qkv[MROWS * QKVN];   // ~100 MB raw qkv (pre-RoPE)
__device__ float g_ao [MROWS * CDIM];   // ~33 MB attention output
__device__ float g_bias[QKVN];

__global__ void bias_compose_kernel(const float* __restrict__ qb,
                                    const float* __restrict__ vb) {
    int n = blockIdx.x * 256 + threadIdx.x;
    if (n >= QKVN) return;
    float v = 0.f;
    if (n < CDIM)            v = qb[n];
    else if (n >= 2 * CDIM)  v = vb[n - 2 * CDIM];
    g_bias[n] = v;
}

// C[m][n] = sum_k A[m][k] * Bm[n][k] + bias[n]
__global__ __launch_bounds__(256) void sgemm_bt_bias(
    const float* __restrict__ A, const float* __restrict__ Bm,
    const float* __restrict__ bias, float* __restrict__ C,
    int M, int N, int K)
{
    __shared__ float As[8][128];
    __shared__ float Bs[8][128];

    int tid = threadIdx.x;
    int m0  = blockIdx.y * 128;
    int n0  = blockIdx.x * 128;
    int tty = tid >> 4, ttx = tid & 15;

    int lrow = tid >> 1;
    int lcol = (tid & 1) * 4;
    const float* Ap = A  + (size_t)(m0 + lrow) * K + lcol;
    const float* Bp = Bm + (size_t)(n0 + lrow) * K + lcol;
    bool aval = (m0 + lrow) < M;

    float acc[8][8];
    #pragma unroll
    for (int i = 0; i < 8; i++)
        #pragma unroll
        for (int j = 0; j < 8; j++) acc[i][j] = 0.f;

    for (int k0 = 0; k0 < K; k0 += 8) {
        float4 av = aval ? *(const float4*)(Ap + k0) : make_float4(0,0,0,0);
        float4 bv = *(const float4*)(Bp + k0);
        __syncthreads();
        As[lcol+0][lrow] = av.x; As[lcol+1][lrow] = av.y;
        As[lcol+2][lrow] = av.z; As[lcol+3][lrow] = av.w;
        Bs[lcol+0][lrow] = bv.x; Bs[lcol+1][lrow] = bv.y;
        Bs[lcol+2][lrow] = bv.z; Bs[lcol+3][lrow] = bv.w;
        __syncthreads();

        #pragma unroll
        for (int k = 0; k < 8; k++) {
            float a[8], b[8];
            *(float4*)&a[0] = *(const float4*)&As[k][tty*8];
            *(float4*)&a[4] = *(const float4*)&As[k][tty*8 + 4];
            *(float4*)&b[0] = *(const float4*)&Bs[k][ttx*8];
            *(float4*)&b[4] = *(const float4*)&Bs[k][ttx*8 + 4];
            #pragma unroll
            for (int i = 0; i < 8; i++)
                #pragma unroll
                for (int j = 0; j < 8; j++)
                    acc[i][j] = fmaf(a[i], b[j], acc[i][j]);
        }
    }

    #pragma unroll
    for (int i = 0; i < 8; i++) {
        int m = m0 + tty*8 + i;
        if (m < M) {
            float* cp = C + (size_t)m * N + n0 + ttx*8;
            #pragma unroll
            for (int j = 0; j < 8; j++) cp[j] = acc[i][j] + bias[n0 + ttx*8 + j];
        }
    }
}

__device__ __forceinline__ void load_rope_tile(
    float (*dstT)[SM_STRIDE], const float* __restrict__ pos,
    int b, int h, int row_base, int comp_off, int tid)
{
    for (int u = tid; u < 512; u += 256) {
        int row = u >> 3;
        int d   = (u & 7) * 4;          // d in [0,32)
        int lg  = row_base + row;
        float4 va = {0,0,0,0}, vb = {0,0,0,0};
        float p0 = 0.f, p1 = 0.f;
        if (lg < L_SEQ) {
            const float* src = g_qkv + (size_t)(b * L_SEQ + lg) * QKVN
                               + comp_off + h * HDIM;
            va = *(const float4*)(src + d);
            vb = *(const float4*)(src + d + 32);
            p0 = pos[(size_t)(b * L_SEQ + lg) * 2 + 0];
            p1 = pos[(size_t)(b * L_SEQ + lg) * 2 + 1];
        }
        const float* xa = (const float*)&va;
        const float* xb = (const float*)&vb;
        #pragma unroll
        for (int j = 0; j < 4; j++) {
            int fi = (d + j) & 15;
            float invf = __expf(-0.5756462732485115f * (float)fi); // 10000^(-fi/16)
            float sa, ca, sb, cb;
            __sincosf(p0 * invf, &sa, &ca);
            __sincosf(p1 * invf, &sb, &cb);
            dstT[d + j][row]      = xa[j] * ca - xb[j] * sa;
            dstT[d + 32 + j][row] = xb[j] * cb + xa[j] * sb;
        }
    }
}

__global__ __launch_bounds__(256) void attn_kernel(
    const float* __restrict__ pos, float* __restrict__ ao)
{
    extern __shared__ float sm[];
    float (*QsT)[SM_STRIDE] = (float(*)[SM_STRIDE])(sm);                  // [d][row]
    float (*KsT)[SM_STRIDE] = (float(*)[SM_STRIDE])(sm + 64*SM_STRIDE);   // [d][key]
    float (*Vs )[SM_STRIDE] = (float(*)[SM_STRIDE])(sm + 2*64*SM_STRIDE); // [key][d]
    float (*PsT)[SM_STRIDE] = (float(*)[SM_STRIDE])(sm + 3*64*SM_STRIDE); // [key][row]

    int qt = blockIdx.x, h = blockIdx.y, b = blockIdx.z;
    int tid = threadIdx.x;
    int ty = tid >> 4, tx = tid & 15;
    int q0 = qt * 64;

    load_rope_tile(QsT, pos, b, h, q0, 0, tid);

    float O[4][4] = {};
    float mrun[4], lrun[4];
    #pragma unroll
    for (int i = 0; i < 4; i++) { mrun[i] = -1e30f; lrun[i] = 0.f; }

    const int NT = (L_SEQ + 63) / 64;   // 11
    for (int kt = 0; kt < NT; kt++) {
        int k0 = kt * 64;
        __syncthreads();

        load_rope_tile(KsT, pos, b, h, k0, CDIM, tid);
        for (int u = tid; u < 1024; u += 256) {
            int row = u >> 4, c4 = (u & 15) << 2;
            int lg = k0 + row;
            float4 v = {0,0,0,0};
            if (lg < L_SEQ)
                v = *(const float4*)(g_qkv + (size_t)(b*L_SEQ + lg)*QKVN
                                     + 2*CDIM + h*HDIM + c4);
            *(float4*)&Vs[row][c4] = v;
        }
        __syncthreads();

        float sacc[4][4] = {};
        #pragma unroll 8
        for (int d = 0; d < 64; d++) {
            float4 a  = *(const float4*)&QsT[d][ty*4];
            float4 bq = *(const float4*)&KsT[d][tx*4];
            float av[4] = {a.x, a.y, a.z, a.w};
            float bv[4] = {bq.x, bq.y, bq.z, bq.w};
            #pragma unroll
            for (int i = 0; i < 4; i++)
                #pragma unroll
                for (int j = 0; j < 4; j++)
                    sacc[i][j] = fmaf(av[i], bv[j], sacc[i][j]);
        }
        #pragma unroll
        for (int i = 0; i < 4; i++)
            #pragma unroll
            for (int j = 0; j < 4; j++) {
                float s = sacc[i][j] * 0.125f;
                if (k0 + tx*4 + j >= L_SEQ) s = -1e30f;
                sacc[i][j] = s;
            }

        #pragma unroll
        for (int i = 0; i < 4; i++) {
            float mx = fmaxf(fmaxf(sacc[i][0], sacc[i][1]),
                             fmaxf(sacc[i][2], sacc[i][3]));
            #pragma unroll
            for (int off = 8; off >= 1; off >>= 1)
                mx = fmaxf(mx, __shfl_xor_sync(0xffffffffu, mx, off, 16));
            float m_new = fmaxf(mrun[i], mx);
            float alpha = __expf(mrun[i] - m_new);
            float rsum = 0.f;
            #pragma unroll
            for (int j = 0; j < 4; j++) {
                float p = __expf(sacc[i][j] - m_new);
                sacc[i][j] = p;
                rsum += p;
            }
            #pragma unroll
            for (int off = 8; off >= 1; off >>= 1)
                rsum += __shfl_xor_sync(0xffffffffu, rsum, off, 16);
            lrun[i] = lrun[i] * alpha + rsum;
            mrun[i] = m_new;
            #pragma unroll
            for (int j = 0; j < 4; j++) O[i][j] *= alpha;
            #pragma unroll
            for (int j = 0; j < 4; j++) PsT[tx*4 + j][ty*4 + i] = sacc[i][j];
        }
        __syncthreads();

        #pragma unroll 8
        for (int j = 0; j < 64; j++) {
            float4 a  = *(const float4*)&PsT[j][ty*4];
            float4 v4 = *(const float4*)&Vs[j][tx*4];
            float av[4] = {a.x, a.y, a.z, a.w};
            float vv[4] = {v4.x, v4.y, v4.z, v4.w};
            #pragma unroll
            for (int i = 0; i < 4; i++)
                #pragma unroll
                for (int jj = 0; jj < 4; jj++)
                    O[i][jj] = fmaf(av[i], vv[jj], O[i][jj]);
        }
    }

    #pragma unroll
    for (int i = 0; i < 4; i++) {
        int lg = q0 + ty*4 + i;
        if (lg < L_SEQ) {
            float inv_l = 1.0f / lrun[i];
            float4 o4 = make_float4(O[i][0]*inv_l, O[i][1]*inv_l,
                                    O[i][2]*inv_l, O[i][3]*inv_l);
            *(float4*)(ao + (size_t)(b*L_SEQ + lg)*CDIM + h*HDIM + tx*4) = o4;
        }
    }
}

extern "C" void kernel_launch(void* const* d_in, const int* in_sizes, int n_in,
                              void* d_out, int out_size)
{
    const float* x    = (const float*)d_in[0];
    const float* pos  = (const float*)d_in[1];
    const float* wqkv = (const float*)d_in[2];
    const float* qb   = (const float*)d_in[3];
    const float* vb   = (const float*)d_in[4];
    const float* wo   = (const float*)d_in[5];
    const float* bo   = (const float*)d_in[6];
    float* out = (float*)d_out;

    float *qkv_p, *ao_p, *bias_p;
    cudaGetSymbolAddress((void**)&qkv_p,  g_qkv);
    cudaGetSymbolAddress((void**)&ao_p,   g_ao);
    cudaGetSymbolAddress((void**)&bias_p, g_bias);

    bias_compose_kernel<<<(QKVN + 255)/256, 256>>>(qb, vb);

    dim3 g1(QKVN / 128, (MROWS + 127) / 128);
    sgemm_bt_bias<<<g1, 256>>>(x, wqkv, bias_p, qkv_p, MROWS, QKVN, CDIM);

    int smem_bytes = 4 * 64 * SM_STRIDE * (int)sizeof(float);   // 69632
    cudaFuncSetAttribute(attn_kernel,
                         cudaFuncAttributeMaxDynamicSharedMemorySize, smem_bytes);
    attn_kernel<<<dim3((L_SEQ + 63)/64, NHEADS, BATCH), 256, smem_bytes>>>(pos, ao_p);

    dim3 g2(CDIM / 128, (MROWS + 127) / 128);
    sgemm_bt_bias<<<g2, 256>>>(ao_p, wo, bo, out, MROWS, CDIM, CDIM);
}

// round 4
// speedup vs baseline: 1.2524x; 1.2524x over previous
#include <cuda_runtime.h>
#include <cstdint>
#include <mma.h>
#include <math.h>

using namespace nvcuda;

#define BATCH   8
#define L_SEQ   680
#define NHEADS  24
#define HDIM    64
#define CDIM    1536
#define MROWS   (BATCH * L_SEQ)      // 5440
#define QKVN    (3 * CDIM)           // 4608
#define SM_STRIDE 68

// GEMM tiling
#define BM 128
#define BN 128
#define BK 16
#define TLD 20          // smem leading dim for k-tiles (16 + 4 pad)
#define EPLD 132        // epilogue staging leading dim

__device__ float g_qkv[MROWS * QKVN];   // ~100 MB raw qkv (pre-RoPE)
__device__ float g_ao [MROWS * CDIM];   // ~33 MB attention output
__device__ float g_bias[QKVN];

// ---------------------------------------------------------------------------
__global__ void bias_compose_kernel(const float* __restrict__ qb,
                                    const float* __restrict__ vb) {
    int n = blockIdx.x * 256 + threadIdx.x;
    if (n >= QKVN) return;
    float v = 0.f;
    if (n < CDIM)            v = qb[n];
    else if (n >= 2 * CDIM)  v = vb[n - 2 * CDIM];
    g_bias[n] = v;
}

// ---------------------------------------------------------------------------
__device__ __forceinline__ void cp_async16(float* smem, const float* g, bool pred) {
    unsigned int saddr = (unsigned int)__cvta_generic_to_shared(smem);
    int sz = pred ? 16 : 0;
    asm volatile("cp.async.cg.shared.global [%0], [%1], 16, %2;\n"
                 :: "r"(saddr), "l"(g), "r"(sz));
}
__device__ __forceinline__ void cp_commit() {
    asm volatile("cp.async.commit_group;\n");
}
template <int N>
__device__ __forceinline__ void cp_wait() {
    asm volatile("cp.async.wait_group %0;\n" :: "n"(N));
}

// ---------------------------------------------------------------------------
// C[m][n] = sum_k A[m][k] * Bm[n][k] + bias[n]     (tf32 tensor cores)
// A: [M][K] row-major, Bm: [N][K] row-major. 128x128x16 tiles, 8 warps.
// ---------------------------------------------------------------------------
__global__ __launch_bounds__(256) void gemm_tf32_bt_bias(
    const float* __restrict__ A, const float* __restrict__ Bm,
    const float* __restrict__ bias, float* __restrict__ C,
    int M, int N, int K)
{
    extern __shared__ float sm[];
    float* As = sm;                    // [2][BM][TLD]
    float* Bs = sm + 2 * BM * TLD;     // [2][BN][TLD]
    // epilogue reuses sm as [BM][EPLD]

    const int tid  = threadIdx.x;
    const int wid  = tid >> 5;
    const int m0   = blockIdx.y * BM;
    const int n0   = blockIdx.x * BN;
    const int wm   = wid >> 2;         // 0..1
    const int wn   = wid & 3;          // 0..3

    const int lrow = tid >> 1;
    const int lcol = (tid & 1) * 8;
    const bool arow_ok = (m0 + lrow) < M;
    const float* Ag = A  + (size_t)(m0 + lrow) * K + lcol;
    const float* Bg = Bm + (size_t)(n0 + lrow) * K + lcol;

    wmma::fragment<wmma::accumulator, 16, 16, 8, float> acc[4][2];
    #pragma unroll
    for (int i = 0; i < 4; i++)
        #pragma unroll
        for (int j = 0; j < 2; j++)
            wmma::fill_fragment(acc[i][j], 0.0f);

    const int nk = K / BK;

    {
        float* a_dst = As + lrow * TLD + lcol;
        float* b_dst = Bs + lrow * TLD + lcol;
        cp_async16(a_dst,     Ag,     arow_ok);
        cp_async16(a_dst + 4, Ag + 4, arow_ok);
        cp_async16(b_dst,     Bg,     true);
        cp_async16(b_dst + 4, Bg + 4, true);
        cp_commit();
    }

    for (int kt = 0; kt < nk; kt++) {
        if (kt + 1 < nk) {
            int nb = (kt + 1) & 1;
            int koff = (kt + 1) * BK;
            float* a_dst = As + nb * BM * TLD + lrow * TLD + lcol;
            float* b_dst = Bs + nb * BN * TLD + lrow * TLD + lcol;
            cp_async16(a_dst,     Ag + koff,     arow_ok);
            cp_async16(a_dst + 4, Ag + koff + 4, arow_ok);
            cp_async16(b_dst,     Bg + koff,     true);
            cp_async16(b_dst + 4, Bg + koff + 4, true);
            cp_commit();
            cp_wait<1>();
        } else {
            cp_wait<0>();
        }
        __syncthreads();

        const float* ab = As + (kt & 1) * BM * TLD;
        const float* bb = Bs + (kt & 1) * BN * TLD;

        #pragma unroll
        for (int ks = 0; ks < 2; ks++) {
            wmma::fragment<wmma::matrix_a, 16, 16, 8, wmma::precision::tf32,
                           wmma::row_major> af[4];
            wmma::fragment<wmma::matrix_b, 16, 16, 8, wmma::precision::tf32,
                           wmma::col_major> bf[2];
            #pragma unroll
            for (int i = 0; i < 4; i++) {
                wmma::load_matrix_sync(af[i],
                    ab + (wm * 64 + i * 16) * TLD + ks * 8, TLD);
                #pragma unroll
                for (int t = 0; t < af[i].num_elements; t++)
                    af[i].x[t] = wmma::__float_to_tf32(af[i].x[t]);
            }
            #pragma unroll
            for (int j = 0; j < 2; j++) {
                wmma::load_matrix_sync(bf[j],
                    bb + (wn * 32 + j * 16) * TLD + ks * 8, TLD);
                #pragma unroll
                for (int t = 0; t < bf[j].num_elements; t++)
                    bf[j].x[t] = wmma::__float_to_tf32(bf[j].x[t]);
            }
            #pragma unroll
            for (int i = 0; i < 4; i++)
                #pragma unroll
                for (int j = 0; j < 2; j++)
                    wmma::mma_sync(acc[i][j], af[i], bf[j], acc[i][j]);
        }
        __syncthreads();
    }

    // epilogue: stage to smem, add bias, vectorized writeout
    #pragma unroll
    for (int i = 0; i < 4; i++)
        #pragma unroll
        for (int j = 0; j < 2; j++)
            wmma::store_matrix_sync(
                sm + (wm * 64 + i * 16) * EPLD + wn * 32 + j * 16,
                acc[i][j], EPLD, wmma::mem_row_major);
    __syncthreads();

    {
        int r = tid >> 1;
        int cseg = (tid & 1) * 64;
        int m = m0 + r;
        if (m < M) {
            float* cp = C + (size_t)m * N + n0 + cseg;
            const float* ep = sm + r * EPLD + cseg;
            const float* bp = bias + n0 + cseg;
            #pragma unroll
            for (int j = 0; j < 16; j++) {
                float4 v = *(const float4*)(ep + j * 4);
                v.x += bp[j * 4 + 0]; v.y += bp[j * 4 + 1];
                v.z += bp[j * 4 + 2]; v.w += bp[j * 4 + 3];
                *(float4*)(cp + j * 4) = v;
            }
        }
    }
}

// ---------------------------------------------------------------------------
// Flash attention with RoPE applied on-the-fly (fp32 FFMA; tensorize next)
// ---------------------------------------------------------------------------
__device__ __forceinline__ void load_rope_tile(
    float (*dstT)[SM_STRIDE], const float* __restrict__ pos,
    int b, int h, int row_base, int comp_off, int tid)
{
    for (int u = tid; u < 512; u += 256) {
        int row = u >> 3;
        int d   = (u & 7) * 4;          // d in [0,32)
        int lg  = row_base + row;
        float4 va = {0,0,0,0}, vb = {0,0,0,0};
        float p0 = 0.f, p1 = 0.f;
        if (lg < L_SEQ) {
            const float* src = g_qkv + (size_t)(b * L_SEQ + lg) * QKVN
                               + comp_off + h * HDIM;
            va = *(const float4*)(src + d);
            vb = *(const float4*)(src + d + 32);
            p0 = pos[(size_t)(b * L_SEQ + lg) * 2 + 0];
            p1 = pos[(size_t)(b * L_SEQ + lg) * 2 + 1];
        }
        const float* xa = (const float*)&va;
        const float* xb = (const float*)&vb;
        #pragma unroll
        for (int j = 0; j < 4; j++) {
            int fi = (d + j) & 15;
            float invf = __expf(-0.5756462732485115f * (float)fi); // 10000^(-fi/16)
            float sa, ca, sb, cb;
            __sincosf(p0 * invf, &sa, &ca);
            __sincosf(p1 * invf, &sb, &cb);
            dstT[d + j][row]      = xa[j] * ca - xb[j] * sa;
            dstT[d + 32 + j][row] = xb[j] * cb + xa[j] * sb;
        }
    }
}

__global__ __launch_bounds__(256) void attn_kernel(
    const float* __restrict__ pos, float* __restrict__ ao)
{
    extern __shared__ float smf[];
    float (*QsT)[SM_STRIDE] = (float(*)[SM_STRIDE])(smf);
    float (*KsT)[SM_STRIDE] = (float(*)[SM_STRIDE])(smf + 64*SM_STRIDE);
    float (*Vs )[SM_STRIDE] = (float(*)[SM_STRIDE])(smf + 2*64*SM_STRIDE);
    float (*PsT)[SM_STRIDE] = (float(*)[SM_STRIDE])(smf + 3*64*SM_STRIDE);

    int qt = blockIdx.x, h = blockIdx.y, b = blockIdx.z;
    int tid = threadIdx.x;
    int ty = tid >> 4, tx = tid & 15;
    int q0 = qt * 64;

    load_rope_tile(QsT, pos, b, h, q0, 0, tid);

    float O[4][4] = {};
    float mrun[4], lrun[4];
    #pragma unroll
    for (int i = 0; i < 4; i++) { mrun[i] = -1e30f; lrun[i] = 0.f; }

    const int NT = (L_SEQ + 63) / 64;   // 11
    for (int kt = 0; kt < NT; kt++) {
        int k0 = kt * 64;
        __syncthreads();

        load_rope_tile(KsT, pos, b, h, k0, CDIM, tid);
        for (int u = tid; u < 1024; u += 256) {
            int row = u >> 4, c4 = (u & 15) << 2;
            int lg = k0 + row;
            float4 v = {0,0,0,0};
            if (lg < L_SEQ)
                v = *(const float4*)(g_qkv + (size_t)(b*L_SEQ + lg)*QKVN
                                     + 2*CDIM + h*HDIM + c4);
            *(float4*)&Vs[row][c4] = v;
        }
        __syncthreads();

        float sacc[4][4] = {};
        #pragma unroll 8
        for (int d = 0; d < 64; d++) {
            float4 a  = *(const float4*)&QsT[d][ty*4];
            float4 bq = *(const float4*)&KsT[d][tx*4];
            float av[4] = {a.x, a.y, a.z, a.w};
            float bv[4] = {bq.x, bq.y, bq.z, bq.w};
            #pragma unroll
            for (int i = 0; i < 4; i++)
                #pragma unroll
                for (int j = 0; j < 4; j++)
                    sacc[i][j] = fmaf(av[i], bv[j], sacc[i][j]);
        }
        #pragma unroll
        for (int i = 0; i < 4; i++)
            #pragma unroll
            for (int j = 0; j < 4; j++) {
                float s = sacc[i][j] * 0.125f;
                if (k0 + tx*4 + j >= L_SEQ) s = -1e30f;
                sacc[i][j] = s;
            }

        #pragma unroll
        for (int i = 0; i < 4; i++) {
            float mx = fmaxf(fmaxf(sacc[i][0], sacc[i][1]),
                             fmaxf(sacc[i][2], sacc[i][3]));
            #pragma unroll
            for (int off = 8; off >= 1; off >>= 1)
                mx = fmaxf(mx, __shfl_xor_sync(0xffffffffu, mx, off, 16));
            float m_new = fmaxf(mrun[i], mx);
            float alpha = __expf(mrun[i] - m_new);
            float rsum = 0.f;
            #pragma unroll
            for (int j = 0; j < 4; j++) {
                float p = __expf(sacc[i][j] - m_new);
                sacc[i][j] = p;
                rsum += p;
            }
            #pragma unroll
            for (int off = 8; off >= 1; off >>= 1)
                rsum += __shfl_xor_sync(0xffffffffu, rsum, off, 16);
            lrun[i] = lrun[i] * alpha + rsum;
            mrun[i] = m_new;
            #pragma unroll
            for (int j = 0; j < 4; j++) O[i][j] *= alpha;
            #pragma unroll
            for (int j = 0; j < 4; j++) PsT[tx*4 + j][ty*4 + i] = sacc[i][j];
        }
        __syncthreads();

        #pragma unroll 8
        for (int j = 0; j < 64; j++) {
            float4 a  = *(const float4*)&PsT[j][ty*4];
            float4 v4 = *(const float4*)&Vs[j][tx*4];
            float av[4] = {a.x, a.y, a.z, a.w};
            float vv[4] = {v4.x, v4.y, v4.z, v4.w};
            #pragma unroll
            for (int i = 0; i < 4; i++)
                #pragma unroll
                for (int jj = 0; jj < 4; jj++)
                    O[i][jj] = fmaf(av[i], vv[jj], O[i][jj]);
        }
    }

    #pragma unroll
    for (int i = 0; i < 4; i++) {
        int lg = q0 + ty*4 + i;
        if (lg < L_SEQ) {
            float inv_l = 1.0f / lrun[i];
            float4 o4 = make_float4(O[i][0]*inv_l, O[i][1]*inv_l,
                                    O[i][2]*inv_l, O[i][3]*inv_l);
            *(float4*)(ao + (size_t)(b*L_SEQ + lg)*CDIM + h*HDIM + tx*4) = o4;
        }
    }
}

// ---------------------------------------------------------------------------
extern "C" void kernel_launch(void* const* d_in, const int* in_sizes, int n_in,
                              void* d_out, int out_size)
{
    const float* x    = (const float*)d_in[0];
    const float* pos  = (const float*)d_in[1];
    const float* wqkv = (const float*)d_in[2];
    const float* qb   = (const float*)d_in[3];
    const float* vb   = (const float*)d_in[4];
    const float* wo   = (const float*)d_in[5];
    const float* bo   = (const float*)d_in[6];
    float* out = (float*)d_out;

    float *qkv_p, *ao_p, *bias_p;
    cudaGetSymbolAddress((void**)&qkv_p,  g_qkv);
    cudaGetSymbolAddress((void**)&ao_p,   g_ao);
    cudaGetSymbolAddress((void**)&bias_p, g_bias);

    bias_compose_kernel<<<(QKVN + 255)/256, 256>>>(qb, vb);

    int smem_gemm = BM * EPLD * (int)sizeof(float);   // 67584
    cudaFuncSetAttribute(gemm_tf32_bt_bias,
                         cudaFuncAttributeMaxDynamicSharedMemorySize, smem_gemm);

    dim3 g1(QKVN / BN, (MROWS + BM - 1) / BM);
    gemm_tf32_bt_bias<<<g1, 256, smem_gemm>>>(x, wqkv, bias_p, qkv_p,
                                              MROWS, QKVN, CDIM);

    int smem_attn = 4 * 64 * SM_STRIDE * (int)sizeof(float);   // 69632
    cudaFuncSetAttribute(attn_kernel,
                         cudaFuncAttributeMaxDynamicSharedMemorySize, smem_attn);
    attn_kernel<<<dim3((L_SEQ + 63)/64, NHEADS, BATCH), 256, smem_attn>>>(pos, ao_p);

    dim3 g2(CDIM / BN, (MROWS + BM - 1) / BM);
    gemm_tf32_bt_bias<<<g2, 256, smem_gemm>>>(ao_p, wo, bo, out,
                                              MROWS, CDIM, CDIM);
}

// round 5
// speedup vs baseline: 1.3192x; 1.0534x over previous
#include <cuda_runtime.h>
#include <cstdint>
#include <mma.h>
#include <math.h>

using namespace nvcuda;

#define BATCH   8
#define L_SEQ   680
#define NHEADS  24
#define HDIM    64
#define CDIM    1536
#define MROWS   (BATCH * L_SEQ)      // 5440
#define QKVN    (3 * CDIM)           // 4608
#define SM_STRIDE 68

// GEMM tiling
#define BM 128
#define BN 128
#define BK 32
#define TLD 36          // smem leading dim for k-tiles (32 + 4 pad)
#define EPLD 132        // epilogue staging leading dim (64-row chunks)

__device__ float g_qkv[MROWS * QKVN];   // ~100 MB raw qkv (pre-RoPE)
__device__ float g_ao [MROWS * CDIM];   // ~33 MB attention output
__device__ float g_bias[QKVN];

// ---------------------------------------------------------------------------
__global__ void bias_compose_kernel(const float* __restrict__ qb,
                                    const float* __restrict__ vb) {
    int n = blockIdx.x * 256 + threadIdx.x;
    if (n >= QKVN) return;
    float v = 0.f;
    if (n < CDIM)            v = qb[n];
    else if (n >= 2 * CDIM)  v = vb[n - 2 * CDIM];
    g_bias[n] = v;
}

// ---------------------------------------------------------------------------
__device__ __forceinline__ void cp_async16(float* smem, const float* g, bool pred) {
    unsigned int saddr = (unsigned int)__cvta_generic_to_shared(smem);
    int sz = pred ? 16 : 0;
    asm volatile("cp.async.cg.shared.global [%0], [%1], 16, %2;\n"
                 :: "r"(saddr), "l"(g), "r"(sz));
}
__device__ __forceinline__ void cp_commit() {
    asm volatile("cp.async.commit_group;\n");
}
template <int N>
__device__ __forceinline__ void cp_wait() {
    asm volatile("cp.async.wait_group %0;\n" :: "n"(N));
}

// ---------------------------------------------------------------------------
// C[m][n] = sum_k A[m][k] * Bm[n][k] + bias[n]     (tf32 tensor cores)
// A: [M][K] row-major, Bm: [N][K] row-major. 128x128x32 tiles, 8 warps,
// double-buffered cp.async, 2 CTAs/SM.
// ---------------------------------------------------------------------------
__global__ __launch_bounds__(256, 2) void gemm_tf32_bt_bias(
    const float* __restrict__ A, const float* __restrict__ Bm,
    const float* __restrict__ bias, float* __restrict__ C,
    int M, int N, int K)
{
    extern __shared__ float sm[];
    float* As = sm;                    // [2][BM][TLD] = 9216 floats
    float* Bs = sm + 2 * BM * TLD;     // [2][BN][TLD] = 9216 floats
    // epilogue reuses sm as [64][EPLD] (33792 B < 73728 B allocated)

    const int tid  = threadIdx.x;
    const int wid  = tid >> 5;
    const int m0   = blockIdx.y * BM;
    const int n0   = blockIdx.x * BN;
    const int wm   = wid >> 2;         // 0..1  (64 rows)
    const int wn   = wid & 3;          // 0..3  (32 cols)

    // load mapping: row = tid>>1 (0..127), col base = (tid&1)*16 -> 4 float4s
    const int lrow = tid >> 1;
    const int lcol = (tid & 1) * 16;
    const bool arow_ok = (m0 + lrow) < M;
    const float* Ag = A  + (size_t)(m0 + lrow) * K + lcol;
    const float* Bg = Bm + (size_t)(n0 + lrow) * K + lcol;

    wmma::fragment<wmma::accumulator, 16, 16, 8, float> acc[4][2];
    #pragma unroll
    for (int i = 0; i < 4; i++)
        #pragma unroll
        for (int j = 0; j < 2; j++)
            wmma::fill_fragment(acc[i][j], 0.0f);

    const int nk = K / BK;

    // prologue: tile 0 -> buf 0
    {
        float* a_dst = As + lrow * TLD + lcol;
        float* b_dst = Bs + lrow * TLD + lcol;
        #pragma unroll
        for (int c = 0; c < 4; c++) {
            cp_async16(a_dst + c * 4, Ag + c * 4, arow_ok);
            cp_async16(b_dst + c * 4, Bg + c * 4, true);
        }
        cp_commit();
    }

    for (int kt = 0; kt < nk; kt++) {
        if (kt + 1 < nk) {
            int nb = (kt + 1) & 1;
            int koff = (kt + 1) * BK;
            float* a_dst = As + nb * BM * TLD + lrow * TLD + lcol;
            float* b_dst = Bs + nb * BM * TLD + lrow * TLD + lcol;
            #pragma unroll
            for (int c = 0; c < 4; c++) {
                cp_async16(a_dst + c * 4, Ag + koff + c * 4, arow_ok);
                cp_async16(b_dst + c * 4, Bg + koff + c * 4, true);
            }
            cp_commit();
            cp_wait<1>();
        } else {
            cp_wait<0>();
        }
        __syncthreads();

        const float* ab = As + (kt & 1) * BM * TLD;
        const float* bb = Bs + (kt & 1) * BM * TLD;

        #pragma unroll
        for (int ks = 0; ks < 4; ks++) {
            wmma::fragment<wmma::matrix_a, 16, 16, 8, wmma::precision::tf32,
                           wmma::row_major> af[4];
            wmma::fragment<wmma::matrix_b, 16, 16, 8, wmma::precision::tf32,
                           wmma::col_major> bf[2];
            #pragma unroll
            for (int i = 0; i < 4; i++) {
                wmma::load_matrix_sync(af[i],
                    ab + (wm * 64 + i * 16) * TLD + ks * 8, TLD);
                #pragma unroll
                for (int t = 0; t < af[i].num_elements; t++)
                    af[i].x[t] = wmma::__float_to_tf32(af[i].x[t]);
            }
            #pragma unroll
            for (int j = 0; j < 2; j++) {
                wmma::load_matrix_sync(bf[j],
                    bb + (wn * 32 + j * 16) * TLD + ks * 8, TLD);
                #pragma unroll
                for (int t = 0; t < bf[j].num_elements; t++)
                    bf[j].x[t] = wmma::__float_to_tf32(bf[j].x[t]);
            }
            #pragma unroll
            for (int i = 0; i < 4; i++)
                #pragma unroll
                for (int j = 0; j < 2; j++)
                    wmma::mma_sync(acc[i][j], af[i], bf[j], acc[i][j]);
        }
        __syncthreads();
    }

    // epilogue: two 64-row passes through smem, bias add, float4 writeout
    #pragma unroll
    for (int pass = 0; pass < 2; pass++) {
        if (wm == pass) {
            #pragma unroll
            for (int i = 0; i < 4; i++)
                #pragma unroll
                for (int j = 0; j < 2; j++)
                    wmma::store_matrix_sync(
                        sm + (i * 16) * EPLD + wn * 32 + j * 16,
                        acc[i][j], EPLD, wmma::mem_row_major);
        }
        __syncthreads();
        {
            int r = tid >> 2;                 // 0..63
            int cseg = (tid & 3) * 32;        // 0,32,64,96
            int m = m0 + pass * 64 + r;
            if (m < M) {
                float* cp = C + (size_t)m * N + n0 + cseg;
                const float* ep = sm + r * EPLD + cseg;
                const float* bp = bias + n0 + cseg;
                #pragma unroll
                for (int j = 0; j < 8; j++) {
                    float4 v = *(const float4*)(ep + j * 4);
                    v.x += bp[j * 4 + 0]; v.y += bp[j * 4 + 1];
                    v.z += bp[j * 4 + 2]; v.w += bp[j * 4 + 3];
                    *(float4*)(cp + j * 4) = v;
                }
            }
        }
        __syncthreads();
    }
}

// ---------------------------------------------------------------------------
// Flash attention with RoPE applied on-the-fly (fp32 FFMA; tensorize next)
// ---------------------------------------------------------------------------
__device__ __forceinline__ void load_rope_tile(
    float (*dstT)[SM_STRIDE], const float* __restrict__ pos,
    int b, int h, int row_base, int comp_off, int tid)
{
    for (int u = tid; u < 512; u += 256) {
        int row = u >> 3;
        int d   = (u & 7) * 4;          // d in [0,32)
        int lg  = row_base + row;
        float4 va = {0,0,0,0}, vb = {0,0,0,0};
        float p0 = 0.f, p1 = 0.f;
        if (lg < L_SEQ) {
            const float* src = g_qkv + (size_t)(b * L_SEQ + lg) * QKVN
                               + comp_off + h * HDIM;
            va = *(const float4*)(src + d);
            vb = *(const float4*)(src + d + 32);
            p0 = pos[(size_t)(b * L_SEQ + lg) * 2 + 0];
            p1 = pos[(size_t)(b * L_SEQ + lg) * 2 + 1];
        }
        const float* xa = (const float*)&va;
        const float* xb = (const float*)&vb;
        #pragma unroll
        for (int j = 0; j < 4; j++) {
            int fi = (d + j) & 15;
            float invf = __expf(-0.5756462732485115f * (float)fi); // 10000^(-fi/16)
            float sa, ca, sb, cb;
            __sincosf(p0 * invf, &sa, &ca);
            __sincosf(p1 * invf, &sb, &cb);
            dstT[d + j][row]      = xa[j] * ca - xb[j] * sa;
            dstT[d + 32 + j][row] = xb[j] * cb + xa[j] * sb;
        }
    }
}

__global__ __launch_bounds__(256) void attn_kernel(
    const float* __restrict__ pos, float* __restrict__ ao)
{
    extern __shared__ float smf[];
    float (*QsT)[SM_STRIDE] = (float(*)[SM_STRIDE])(smf);
    float (*KsT)[SM_STRIDE] = (float(*)[SM_STRIDE])(smf + 64*SM_STRIDE);
    float (*Vs )[SM_STRIDE] = (float(*)[SM_STRIDE])(smf + 2*64*SM_STRIDE);
    float (*PsT)[SM_STRIDE] = (float(*)[SM_STRIDE])(smf + 3*64*SM_STRIDE);

    int qt = blockIdx.x, h = blockIdx.y, b = blockIdx.z;
    int tid = threadIdx.x;
    int ty = tid >> 4, tx = tid & 15;
    int q0 = qt * 64;

    load_rope_tile(QsT, pos, b, h, q0, 0, tid);

    float O[4][4] = {};
    float mrun[4], lrun[4];
    #pragma unroll
    for (int i = 0; i < 4; i++) { mrun[i] = -1e30f; lrun[i] = 0.f; }

    const int NT = (L_SEQ + 63) / 64;   // 11
    for (int kt = 0; kt < NT; kt++) {
        int k0 = kt * 64;
        __syncthreads();

        load_rope_tile(KsT, pos, b, h, k0, CDIM, tid);
        for (int u = tid; u < 1024; u += 256) {
            int row = u >> 4, c4 = (u & 15) << 2;
            int lg = k0 + row;
            float4 v = {0,0,0,0};
            if (lg < L_SEQ)
                v = *(const float4*)(g_qkv + (size_t)(b*L_SEQ + lg)*QKVN
                                     + 2*CDIM + h*HDIM + c4);
            *(float4*)&Vs[row][c4] = v;
        }
        __syncthreads();

        float sacc[4][4] = {};
        #pragma unroll 8
        for (int d = 0; d < 64; d++) {
            float4 a  = *(const float4*)&QsT[d][ty*4];
            float4 bq = *(const float4*)&KsT[d][tx*4];
            float av[4] = {a.x, a.y, a.z, a.w};
            float bv[4] = {bq.x, bq.y, bq.z, bq.w};
            #pragma unroll
            for (int i = 0; i < 4; i++)
                #pragma unroll
                for (int j = 0; j < 4; j++)
                    sacc[i][j] = fmaf(av[i], bv[j], sacc[i][j]);
        }
        #pragma unroll
        for (int i = 0; i < 4; i++)
            #pragma unroll
            for (int j = 0; j < 4; j++) {
                float s = sacc[i][j] * 0.125f;
                if (k0 + tx*4 + j >= L_SEQ) s = -1e30f;
                sacc[i][j] = s;
            }

        #pragma unroll
        for (int i = 0; i < 4; i++) {
            float mx = fmaxf(fmaxf(sacc[i][0], sacc[i][1]),
                             fmaxf(sacc[i][2], sacc[i][3]));
            #pragma unroll
            for (int off = 8; off >= 1; off >>= 1)
                mx = fmaxf(mx, __shfl_xor_sync(0xffffffffu, mx, off, 16));
            float m_new = fmaxf(mrun[i], mx);
            float alpha = __expf(mrun[i] - m_new);
            float rsum = 0.f;
            #pragma unroll
            for (int j = 0; j < 4; j++) {
                float p = __expf(sacc[i][j] - m_new);
                sacc[i][j] = p;
                rsum += p;
            }
            #pragma unroll
            for (int off = 8; off >= 1; off >>= 1)
                rsum += __shfl_xor_sync(0xffffffffu, rsum, off, 16);
            lrun[i] = lrun[i] * alpha + rsum;
            mrun[i] = m_new;
            #pragma unroll
            for (int j = 0; j < 4; j++) O[i][j] *= alpha;
            #pragma unroll
            for (int j = 0; j < 4; j++) PsT[tx*4 + j][ty*4 + i] = sacc[i][j];
        }
        __syncthreads();

        #pragma unroll 8
        for (int j = 0; j < 64; j++) {
            float4 a  = *(const float4*)&PsT[j][ty*4];
            float4 v4 = *(const float4*)&Vs[j][tx*4];
            float av[4] = {a.x, a.y, a.z, a.w};
            float vv[4] = {v4.x, v4.y, v4.z, v4.w};
            #pragma unroll
            for (int i = 0; i < 4; i++)
                #pragma unroll
                for (int jj = 0; jj < 4; jj++)
                    O[i][jj] = fmaf(av[i], vv[jj], O[i][jj]);
        }
    }

    #pragma unroll
    for (int i = 0; i < 4; i++) {
        int lg = q0 + ty*4 + i;
        if (lg < L_SEQ) {
            float inv_l = 1.0f / lrun[i];
            float4 o4 = make_float4(O[i][0]*inv_l, O[i][1]*inv_l,
                                    O[i][2]*inv_l, O[i][3]*inv_l);
            *(float4*)(ao + (size_t)(b*L_SEQ + lg)*CDIM + h*HDIM + tx*4) = o4;
        }
    }
}

// ---------------------------------------------------------------------------
extern "C" void kernel_launch(void* const* d_in, const int* in_sizes, int n_in,
                              void* d_out, int out_size)
{
    const float* x    = (const float*)d_in[0];
    const float* pos  = (const float*)d_in[1];
    const float* wqkv = (const float*)d_in[2];
    const float* qb   = (const float*)d_in[3];
    const float* vb   = (const float*)d_in[4];
    const float* wo   = (const float*)d_in[5];
    const float* bo   = (const float*)d_in[6];
    float* out = (float*)d_out;

    float *qkv_p, *ao_p, *bias_p;
    cudaGetSymbolAddress((void**)&qkv_p,  g_qkv);
    cudaGetSymbolAddress((void**)&ao_p,   g_ao);
    cudaGetSymbolAddress((void**)&bias_p, g_bias);

    bias_compose_kernel<<<(QKVN + 255)/256, 256>>>(qb, vb);

    int smem_gemm = 4 * BM * TLD * (int)sizeof(float);   // 73728
    cudaFuncSetAttribute(gemm_tf32_bt_bias,
                         cudaFuncAttributeMaxDynamicSharedMemorySize, smem_gemm);

    dim3 g1(QKVN / BN, (MROWS + BM - 1) / BM);
    gemm_tf32_bt_bias<<<g1, 256, smem_gemm>>>(x, wqkv, bias_p, qkv_p,
                                              MROWS, QKVN, CDIM);

    int smem_attn = 4 * 64 * SM_STRIDE * (int)sizeof(float);   // 69632
    cudaFuncSetAttribute(attn_kernel,
                         cudaFuncAttributeMaxDynamicSharedMemorySize, smem_attn);
    attn_kernel<<<dim3((L_SEQ + 63)/64, NHEADS, BATCH), 256, smem_attn>>>(pos, ao_p);

    dim3 g2(CDIM / BN, (MROWS + BM - 1) / BM);
    gemm_tf32_bt_bias<<<g2, 256, smem_gemm>>>(ao_p, wo, bo, out,
                                              MROWS, CDIM, CDIM);
}

// round 7
// speedup vs baseline: 1.3567x; 1.0284x over previous
#include <cuda_runtime.h>
#include <cstdint>
#include <mma.h>
#include <math.h>

using namespace nvcuda;

#define BATCH   8
#define L_SEQ   680
#define NHEADS  24
#define HDIM    64
#define CDIM    1536
#define MROWS   (BATCH * L_SEQ)      // 5440
#define QKVN    (3 * CDIM)           // 4608
#define SM_STRIDE 68

// GEMM tiling
#define BM 128
#define BN 128
#define BK 32
#define TLD 36          // smem leading dim for k-tiles (32 + 4 pad)
#define EPLD 132        // epilogue staging leading dim (64-row chunks)

__device__ float g_qkv[MROWS * QKVN];   // raw qkv (pre-RoPE), fp32
__device__ float g_ao [MROWS * CDIM];   // attention output (tf32-rounded)
__device__ float g_bias[QKVN];
// tf32-pre-rounded operand copies (rounding hoisted out of GEMM mainloop)
__device__ float g_xr   [MROWS * CDIM];   // 33 MB
__device__ float g_wqkvr[QKVN * CDIM];    // 28 MB
__device__ float g_wor  [CDIM * CDIM];    //  9 MB

// ---------------------------------------------------------------------------
__global__ void bias_compose_kernel(const float* __restrict__ qb,
                                    const float* __restrict__ vb) {
    int n = blockIdx.x * 256 + threadIdx.x;
    if (n >= QKVN) return;
    float v = 0.f;
    if (n < CDIM)            v = qb[n];
    else if (n >= 2 * CDIM)  v = vb[n - 2 * CDIM];
    g_bias[n] = v;
}

// y = tf32_round(x), vectorized. n4 = element count / 4.
__global__ __launch_bounds__(256) void round_tf32_kernel(
    const float* __restrict__ x, float* __restrict__ y, int n4)
{
    int i = blockIdx.x * 256 + threadIdx.x;
    if (i >= n4) return;
    float4 v = ((const float4*)x)[i];
    v.x = wmma::__float_to_tf32(v.x);
    v.y = wmma::__float_to_tf32(v.y);
    v.z = wmma::__float_to_tf32(v.z);
    v.w = wmma::__float_to_tf32(v.w);
    ((float4*)y)[i] = v;
}

// ---------------------------------------------------------------------------
__device__ __forceinline__ void cp_async16(float* smem, const float* g, bool pred) {
    unsigned int saddr = (unsigned int)__cvta_generic_to_shared(smem);
    int sz = pred ? 16 : 0;
    asm volatile("cp.async.cg.shared.global [%0], [%1], 16, %2;\n"
                 :: "r"(saddr), "l"(g), "r"(sz));
}
__device__ __forceinline__ void cp_commit() {
    asm volatile("cp.async.commit_group;\n");
}
template <int N>
__device__ __forceinline__ void cp_wait() {
    asm volatile("cp.async.wait_group %0;\n" :: "n"(N));
}

// ---------------------------------------------------------------------------
// C[m][n] = sum_k A[m][k] * Bm[n][k] + bias[n]    (tf32 tensor cores)
// A, Bm MUST be pre-rounded to tf32 values. No conversions in mainloop.
// ---------------------------------------------------------------------------
__global__ __launch_bounds__(256, 2) void gemm_tf32_bt_bias(
    const float* __restrict__ A, const float* __restrict__ Bm,
    const float* __restrict__ bias, float* __restrict__ C,
    int M, int N, int K)
{
    extern __shared__ float sm[];
    float* As = sm;                    // [2][BM][TLD]
    float* Bs = sm + 2 * BM * TLD;     // [2][BN][TLD]

    const int tid  = threadIdx.x;
    const int wid  = tid >> 5;
    const int m0   = blockIdx.y * BM;
    const int n0   = blockIdx.x * BN;
    const int wm   = wid >> 2;         // 0..1  (64 rows)
    const int wn   = wid & 3;          // 0..3  (32 cols)

    const int lrow = tid >> 1;
    const int lcol = (tid & 1) * 16;
    const bool arow_ok = (m0 + lrow) < M;
    const float* Ag = A  + (size_t)(m0 + lrow) * K + lcol;
    const float* Bg = Bm + (size_t)(n0 + lrow) * K + lcol;

    wmma::fragment<wmma::accumulator, 16, 16, 8, float> acc[4][2];
    #pragma unroll
    for (int i = 0; i < 4; i++)
        #pragma unroll
        for (int j = 0; j < 2; j++)
            wmma::fill_fragment(acc[i][j], 0.0f);

    const int nk = K / BK;

    {
        float* a_dst = As + lrow * TLD + lcol;
        float* b_dst = Bs + lrow * TLD + lcol;
        #pragma unroll
        for (int c = 0; c < 4; c++) {
            cp_async16(a_dst + c * 4, Ag + c * 4, arow_ok);
            cp_async16(b_dst + c * 4, Bg + c * 4, true);
        }
        cp_commit();
    }

    for (int kt = 0; kt < nk; kt++) {
        if (kt + 1 < nk) {
            int nb = (kt + 1) & 1;
            int koff = (kt + 1) * BK;
            float* a_dst = As + nb * BM * TLD + lrow * TLD + lcol;
            float* b_dst = Bs + nb * BM * TLD + lrow * TLD + lcol;
            #pragma unroll
            for (int c = 0; c < 4; c++) {
                cp_async16(a_dst + c * 4, Ag + koff + c * 4, arow_ok);
                cp_async16(b_dst + c * 4, Bg + koff + c * 4, true);
            }
            cp_commit();
            cp_wait<1>();
        } else {
            cp_wait<0>();
        }
        __syncthreads();

        const float* ab = As + (kt & 1) * BM * TLD;
        const float* bb = Bs + (kt & 1) * BM * TLD;

        #pragma unroll
        for (int ks = 0; ks < 4; ks++) {
            wmma::fragment<wmma::matrix_a, 16, 16, 8, wmma::precision::tf32,
                           wmma::row_major> af[4];
            wmma::fragment<wmma::matrix_b, 16, 16, 8, wmma::precision::tf32,
                           wmma::col_major> bf[2];
            #pragma unroll
            for (int i = 0; i < 4; i++)
                wmma::load_matrix_sync(af[i],
                    ab + (wm * 64 + i * 16) * TLD + ks * 8, TLD);
            #pragma unroll
            for (int j = 0; j < 2; j++)
                wmma::load_matrix_sync(bf[j],
                    bb + (wn * 32 + j * 16) * TLD + ks * 8, TLD);
            #pragma unroll
            for (int i = 0; i < 4; i++)
                #pragma unroll
                for (int j = 0; j < 2; j++)
                    wmma::mma_sync(acc[i][j], af[i], bf[j], acc[i][j]);
        }
        __syncthreads();
    }

    // epilogue: two 64-row passes through smem, bias add, float4 writeout
    #pragma unroll
    for (int pass = 0; pass < 2; pass++) {
        if (wm == pass) {
            #pragma unroll
            for (int i = 0; i < 4; i++)
                #pragma unroll
                for (int j = 0; j < 2; j++)
                    wmma::store_matrix_sync(
                        sm + (i * 16) * EPLD + wn * 32 + j * 16,
                        acc[i][j], EPLD, wmma::mem_row_major);
        }
        __syncthreads();
        {
            int r = tid >> 2;                 // 0..63
            int cseg = (tid & 3) * 32;        // 0,32,64,96
            int m = m0 + pass * 64 + r;
            if (m < M) {
                float* cp = C + (size_t)m * N + n0 + cseg;
                const float* ep = sm + r * EPLD + cseg;
                const float* bp = bias + n0 + cseg;
                #pragma unroll
                for (int j = 0; j < 8; j++) {
                    float4 v = *(const float4*)(ep + j * 4);
                    v.x += bp[j * 4 + 0]; v.y += bp[j * 4 + 1];
                    v.z += bp[j * 4 + 2]; v.w += bp[j * 4 + 3];
                    *(float4*)(cp + j * 4) = v;
                }
            }
        }
        __syncthreads();
    }
}

// ---------------------------------------------------------------------------
// Flash attention with RoPE applied on-the-fly (fp32 FFMA)
// Output ao is tf32-rounded (so the 2nd GEMM needs no conversion).
// ---------------------------------------------------------------------------
__device__ __forceinline__ void load_rope_tile(
    float (*dstT)[SM_STRIDE], const float* __restrict__ pos,
    int b, int h, int row_base, int comp_off, int tid)
{
    for (int u = tid; u < 512; u += 256) {
        int row = u >> 3;
        int d   = (u & 7) * 4;          // d in [0,32)
        int lg  = row_base + row;
        float4 va = {0,0,0,0}, vb = {0,0,0,0};
        float p0 = 0.f, p1 = 0.f;
        if (lg < L_SEQ) {
            const float* src = g_qkv + (size_t)(b * L_SEQ + lg) * QKVN
                               + comp_off + h * HDIM;
            va = *(const float4*)(src + d);
            vb = *(const float4*)(src + d + 32);
            p0 = pos[(size_t)(b * L_SEQ + lg) * 2 + 0];
            p1 = pos[(size_t)(b * L_SEQ + lg) * 2 + 1];
        }
        const float* xa = (const float*)&va;
        const float* xb = (const float*)&vb;
        #pragma unroll
        for (int j = 0; j < 4; j++) {
            int fi = (d + j) & 15;
            float invf = __expf(-0.5756462732485115f * (float)fi); // 10000^(-fi/16)
            float sa, ca, sb, cb;
            __sincosf(p0 * invf, &sa, &ca);
            __sincosf(p1 * invf, &sb, &cb);
            dstT[d + j][row]      = xa[j] * ca - xb[j] * sa;
            dstT[d + 32 + j][row] = xb[j] * cb + xa[j] * sb;
        }
    }
}

__global__ __launch_bounds__(256) void attn_kernel(
    const float* __restrict__ pos, float* __restrict__ ao)
{
    extern __shared__ float smf[];
    float (*QsT)[SM_STRIDE] = (float(*)[SM_STRIDE])(smf);
    float (*KsT)[SM_STRIDE] = (float(*)[SM_STRIDE])(smf + 64*SM_STRIDE);
    float (*Vs )[SM_STRIDE] = (float(*)[SM_STRIDE])(smf + 2*64*SM_STRIDE);
    float (*PsT)[SM_STRIDE] = (float(*)[SM_STRIDE])(smf + 3*64*SM_STRIDE);

    int qt = blockIdx.x, h = blockIdx.y, b = blockIdx.z;
    int tid = threadIdx.x;
    int ty = tid >> 4, tx = tid & 15;
    int q0 = qt * 64;

    load_rope_tile(QsT, pos, b, h, q0, 0, tid);

    float O[4][4] = {};
    float mrun[4], lrun[4];
    #pragma unroll
    for (int i = 0; i < 4; i++) { mrun[i] = -1e30f; lrun[i] = 0.f; }

    const int NT = (L_SEQ + 63) / 64;   // 11
    for (int kt = 0; kt < NT; kt++) {
        int k0 = kt * 64;
        __syncthreads();

        load_rope_tile(KsT, pos, b, h, k0, CDIM, tid);
        for (int u = tid; u < 1024; u += 256) {
            int row = u >> 4, c4 = (u & 15) << 2;
            int lg = k0 + row;
            float4 v = {0,0,0,0};
            if (lg < L_SEQ)
                v = *(const float4*)(g_qkv + (size_t)(b*L_SEQ + lg)*QKVN
                                     + 2*CDIM + h*HDIM + c4);
            *(float4*)&Vs[row][c4] = v;
        }
        __syncthreads();

        float sacc[4][4] = {};
        #pragma unroll 8
        for (int d = 0; d < 64; d++) {
            float4 a  = *(const float4*)&QsT[d][ty*4];
            float4 bq = *(const float4*)&KsT[d][tx*4];
            float av[4] = {a.x, a.y, a.z, a.w};
            float bv[4] = {bq.x, bq.y, bq.z, bq.w};
            #pragma unroll
            for (int i = 0; i < 4; i++)
                #pragma unroll
                for (int j = 0; j < 4; j++)
                    sacc[i][j] = fmaf(av[i], bv[j], sacc[i][j]);
        }
        #pragma unroll
        for (int i = 0; i < 4; i++)
            #pragma unroll
            for (int j = 0; j < 4; j++) {
                float s = sacc[i][j] * 0.125f;
                if (k0 + tx*4 + j >= L_SEQ) s = -1e30f;
                sacc[i][j] = s;
            }

        #pragma unroll
        for (int i = 0; i < 4; i++) {
            float mx = fmaxf(fmaxf(sacc[i][0], sacc[i][1]),
                             fmaxf(sacc[i][2], sacc[i][3]));
            #pragma unroll
            for (int off = 8; off >= 1; off >>= 1)
                mx = fmaxf(mx, __shfl_xor_sync(0xffffffffu, mx, off, 16));
            float m_new = fmaxf(mrun[i], mx);
            float alpha = __expf(mrun[i] - m_new);
            float rsum = 0.f;
            #pragma unroll
            for (int j = 0; j < 4; j++) {
                float p = __expf(sacc[i][j] - m_new);
                sacc[i][j] = p;
                rsum += p;
            }
            #pragma unroll
            for (int off = 8; off >= 1; off >>= 1)
                rsum += __shfl_xor_sync(0xffffffffu, rsum, off, 16);
            lrun[i] = lrun[i] * alpha + rsum;
            mrun[i] = m_new;
            #pragma unroll
            for (int j = 0; j < 4; j++) O[i][j] *= alpha;
            #pragma unroll
            for (int j = 0; j < 4; j++) PsT[tx*4 + j][ty*4 + i] = sacc[i][j];
        }
        __syncthreads();

        #pragma unroll 8
        for (int j = 0; j < 64; j++) {
            float4 a  = *(const float4*)&PsT[j][ty*4];
            float4 v4 = *(const float4*)&Vs[j][tx*4];
            float av[4] = {a.x, a.y, a.z, a.w};
            float vv[4] = {v4.x, v4.y, v4.z, v4.w};
            #pragma unroll
            for (int i = 0; i < 4; i++)
                #pragma unroll
                for (int jj = 0; jj < 4; jj++)
                    O[i][jj] = fmaf(av[i], vv[jj], O[i][jj]);
        }
    }

    #pragma unroll
    for (int i = 0; i < 4; i++) {
        int lg = q0 + ty*4 + i;
        if (lg < L_SEQ) {
            float inv_l = 1.0f / lrun[i];
            // tf32-round here so GEMM2 consumes pre-rounded input
            float4 o4 = make_float4(
                wmma::__float_to_tf32(O[i][0]*inv_l),
                wmma::__float_to_tf32(O[i][1]*inv_l),
                wmma::__float_to_tf32(O[i][2]*inv_l),
                wmma::__float_to_tf32(O[i][3]*inv_l));
            *(float4*)(ao + (size_t)(b*L_SEQ + lg)*CDIM + h*HDIM + tx*4) = o4;
        }
    }
}

// ---------------------------------------------------------------------------
extern "C" void kernel_launch(void* const* d_in, const int* in_sizes, int n_in,
                              void* d_out, int out_size)
{
    const float* x    = (const float*)d_in[0];
    const float* pos  = (const float*)d_in[1];
    const float* wqkv = (const float*)d_in[2];
    const float* qb   = (const float*)d_in[3];
    const float* vb   = (const float*)d_in[4];
    const float* wo   = (const float*)d_in[5];
    const float* bo   = (const float*)d_in[6];
    float* out = (float*)d_out;

    float *qkv_p, *ao_p, *bias_p, *xr_p, *wqkvr_p, *wor_p;
    cudaGetSymbolAddress((void**)&qkv_p,   g_qkv);
    cudaGetSymbolAddress((void**)&ao_p,    g_ao);
    cudaGetSymbolAddress((void**)&bias_p,  g_bias);
    cudaGetSymbolAddress((void**)&xr_p,    g_xr);
    cudaGetSymbolAddress((void**)&wqkvr_p, g_wqkvr);
    cudaGetSymbolAddress((void**)&wor_p,   g_wor);

    bias_compose_kernel<<<(QKVN + 255)/256, 256>>>(qb, vb);

    // pre-round operands to tf32 (hoists all CVTs out of GEMM mainloops)
    {
        int n4 = (MROWS * CDIM) / 4;
        round_tf32_kernel<<<(n4 + 255)/256, 256>>>(x, xr_p, n4);
        n4 = (QKVN * CDIM) / 4;
        round_tf32_kernel<<<(n4 + 255)/256, 256>>>(wqkv, wqkvr_p, n4);
        n4 = (CDIM * CDIM) / 4;
        round_tf32_kernel<<<(n4 + 255)/256, 256>>>(wo, wor_p, n4);
    }

    int smem_gemm = 4 * BM * TLD * (int)sizeof(float);   // 73728
    cudaFuncSetAttribute(gemm_tf32_bt_bias,
                         cudaFuncAttributeMaxDynamicSharedMemorySize, smem_gemm);

    dim3 g1(QKVN / BN, (MROWS + BM - 1) / BM);
    gemm_tf32_bt_bias<<<g1, 256, smem_gemm>>>(xr_p, wqkvr_p, bias_p, qkv_p,
                                              MROWS, QKVN, CDIM);

    int smem_attn = 4 * 64 * SM_STRIDE * (int)sizeof(float);   // 69632
    cudaFuncSetAttribute(attn_kernel,
                         cudaFuncAttributeMaxDynamicSharedMemorySize, smem_attn);
    attn_kernel<<<dim3((L_SEQ + 63)/64, NHEADS, BATCH), 256, smem_attn>>>(pos, ao_p);

    dim3 g2(CDIM / BN, (MROWS + BM - 1) / BM);
    gemm_tf32_bt_bias<<<g2, 256, smem_gemm>>>(ao_p, wor_p, bo, out,
                                              MROWS, CDIM, CDIM);
}